// round 15
// baseline (speedup 1.0000x reference)
#include <cuda_runtime.h>
#include <cuda_fp16.h>
#include <cstdint>

// Problem constants (fixed-shape problem: H=8, MH=8, N_NODES=500000)
#define H_DIM 8
#define MH_DIM 8
#define FEAT 64              // H*MH per sign
#define REC 128              // 2 signs * FEAT values per node record
#define MAX_NODES 500000
#define TILE_N 128           // nodes per transpose tile

// Node-major scratch in fp16: [node][sign][h][mh], 256B per node,
// deg-normalization folded in. uint4 type guarantees 16B alignment.
__device__ uint4 g_pk_raw[(size_t)MAX_NODES * REC / 8];

// ---- L2 eviction-priority helpers (cache_hint form) ----
__device__ __forceinline__ uint64_t mk_evict_last_policy() {
    uint64_t pol;
    asm("createpolicy.fractional.L2::evict_last.b64 %0, 1.0;" : "=l"(pol));
    return pol;
}
__device__ __forceinline__ void st_hint_v4(void* p, uint4 v, uint64_t pol) {
    asm volatile("st.global.L2::cache_hint.v4.b32 [%0], {%1,%2,%3,%4}, %5;"
                 :: "l"(p), "r"(v.x), "r"(v.y), "r"(v.z), "r"(v.w), "l"(pol));
}
__device__ __forceinline__ uint4 ld_hint_v4(const void* p, uint64_t pol) {
    uint4 r;
    asm volatile("ld.global.L2::cache_hint.v4.u32 {%0,%1,%2,%3}, [%4], %5;"
                 : "=r"(r.x), "=r"(r.y), "=r"(r.z), "=r"(r.w)
                 : "l"(p), "l"(pol));
    return r;
}

// Swizzled byte offset of (feat f, node n) in the 64x128 float tile
// (row = 512B). x = (f ^ (f>>4)) & 7 applied to bits[6:4]:
//  - phase-1 float4 stores (fixed f, lanes = node groups): conflict-free
//  - phase-2 reads (f = 8c+j, 4 nodes x 8 c per warp): 16 banks -> 2-way max
__device__ __forceinline__ int sw_byte(int f, int n) {
    int x = (f ^ (f >> 4)) & 7;
    return f * 512 + n * 4 + (x << 4) - 2 * ((f * 512 + n * 4) & (x << 4));
}
// (a ^ b) written as a+b-2*(a&b) avoids recomputing; equivalent to XOR since
// x<<4 only touches bits [6:4].

// ---------------------------------------------------------------------------
// Kernel 1 (per sign): transpose [h][mh][N] -> scratch[k][sign][h][mh] fp16,
// folding 1/max(deg,1). Block: 256 threads, tile 128 nodes x 64 features.
// One sign per launch keeps the per-SM TLB working set at ~65 2MB pages
// (64 phi rows = 64 pages, shared by all blocks) < 128 TLB entries.
// ---------------------------------------------------------------------------
__global__ __launch_bounds__(256) void transpose_fold_sign_kernel(
    const float* __restrict__ phi,     // [FEAT][N] for this sign
    const float* __restrict__ deg,     // [N][H]    for this sign
    int sgn8,                          // 0 (pos) or 8 (neg): chunk offset
    int n_nodes)
{
    __shared__ __align__(16) char tile_raw[64 * 512];    // 32KB
    __shared__ float inv[TILE_N][H_DIM];                 // 4KB

    const int k0 = blockIdx.x * TILE_N;
    const int t  = threadIdx.x;
    const uint64_t pol = mk_evict_last_policy();
    const bool full = (k0 + TILE_N <= n_nodes) && ((n_nodes & 3) == 0);

    // ---- inv table: 128 nodes * 8 heads = 1024 values, coalesced ----
    #pragma unroll
    for (int it = 0; it < 4; ++it) {
        int idx  = t + it * 256;            // node*8 + h
        int node = idx >> 3;
        int h    = idx & 7;
        int k    = k0 + node;
        float d  = 1.0f;
        if (k < n_nodes)
            d = __ldcs(deg + (size_t)k * H_DIM + h);
        inv[node][h] = 1.0f / fmaxf(d, 1.0f);
    }
    __syncthreads();

    // ---- phase 1: 64 feat-rows x 32 float4 groups (128 nodes) ----
    if (full) {
        #pragma unroll
        for (int it = 0; it < 8; ++it) {
            int l = t + it * 256;           // 0..2047
            int f = l >> 5;                 // feat row 0..63
            int g = l & 31;                 // float4 group (4 nodes)
            float4 v = __ldcs(reinterpret_cast<const float4*>(
                phi + (size_t)f * n_nodes + k0 + 4 * g));
            *reinterpret_cast<float4*>(tile_raw + sw_byte(f, 4 * g)) = v;
        }
    } else {
        #pragma unroll 4
        for (int it = 0; it < 32; ++it) {
            int l  = t + it * 256;          // 64*128 = 8192 elements
            int f  = l >> 7;
            int kk = l & 127;
            int k  = k0 + kk;
            float v = 0.0f;
            if (k < n_nodes)
                v = __ldcs(phi + (size_t)f * n_nodes + k);
            *reinterpret_cast<float*>(tile_raw + sw_byte(f, kk)) = v;
        }
    }
    __syncthreads();

    // ---- phase 2: 128 nodes x 8 chunks; chunk c = head c = feats 8c..8c+7 ----
    #pragma unroll
    for (int it = 0; it < 4; ++it) {
        int l    = t + it * 256;            // 0..1023
        int node = l >> 3;
        int c    = l & 7;
        int k    = k0 + node;
        if (k < n_nodes) {
            float sc = inv[node][c];
            __half2 hh[4];
            #pragma unroll
            for (int j = 0; j < 8; j += 2) {
                float a = *reinterpret_cast<const float*>(
                              tile_raw + sw_byte(8 * c + j, node)) * sc;
                float b = *reinterpret_cast<const float*>(
                              tile_raw + sw_byte(8 * c + j + 1, node)) * sc;
                hh[j >> 1] = __floats2half2_rn(a, b);
            }
            uint4 val;
            __builtin_memcpy(&val, hh, 16);
            st_hint_v4(g_pk_raw + (size_t)k * (REC / 8) + sgn8 + c, val, pol);
        }
    }
}

// ---------------------------------------------------------------------------
// Kernel 2: gather + dot (champion, byte-identical). 8 threads per query;
// thread j = head j. out layout: [pos: nq*8][neg: nq*8]
// ---------------------------------------------------------------------------
__global__ __launch_bounds__(256) void gather_dot_kernel(
    const float* __restrict__ q_phi,
    const int*   __restrict__ k_indices,
    float* __restrict__ out,
    int nq)
{
    int t = blockIdx.x * blockDim.x + threadIdx.x;
    int i = t >> 3;
    if (i >= nq) return;
    int h = t & 7;

    const uint64_t pol = mk_evict_last_policy();

    int k = __ldcs(k_indices + i);

    const float4* qp = reinterpret_cast<const float4*>(
        q_phi + (size_t)i * FEAT + h * MH_DIM);
    float4 q0 = __ldcs(qp);
    float4 q1 = __ldcs(qp + 1);

    const uint4* rec = g_pk_raw + (size_t)k * (REC / 8);
    uint4 pr = ld_hint_v4(rec + h, pol);
    uint4 nr = ld_hint_v4(rec + 8 + h, pol);

    const __half2* ph = reinterpret_cast<const __half2*>(&pr);
    const __half2* nh = reinterpret_cast<const __half2*>(&nr);

    float2 p0 = __half22float2(ph[0]);
    float2 p1 = __half22float2(ph[1]);
    float2 p2 = __half22float2(ph[2]);
    float2 p3 = __half22float2(ph[3]);
    float2 n0 = __half22float2(nh[0]);
    float2 n1 = __half22float2(nh[1]);
    float2 n2 = __half22float2(nh[2]);
    float2 n3 = __half22float2(nh[3]);

    float dp = q0.x * p0.x + q0.y * p0.y + q0.z * p1.x + q0.w * p1.y
             + q1.x * p2.x + q1.y * p2.y + q1.z * p3.x + q1.w * p3.y;
    float dn = q0.x * n0.x + q0.y * n0.y + q0.z * n1.x + q0.w * n1.y
             + q1.x * n2.x + q1.y * n2.y + q1.z * n3.x + q1.w * n3.y;

    __stcs(out + (size_t)i * H_DIM + h, dp);
    __stcs(out + (size_t)nq * H_DIM + (size_t)i * H_DIM + h, dn);
}

extern "C" void kernel_launch(void* const* d_in, const int* in_sizes, int n_in,
                              void* d_out, int out_size)
{
    const float* q_phi   = (const float*)d_in[0];
    const float* phi_pos = (const float*)d_in[1];
    const float* phi_neg = (const float*)d_in[2];
    const float* deg_pos = (const float*)d_in[3];
    const float* deg_neg = (const float*)d_in[4];
    const int*   k_idx   = (const int*)d_in[5];

    int nq      = in_sizes[5];                    // k_indices has N_Q elements
    int n_nodes = in_sizes[3] / H_DIM;            // deg_pos is [N][H]
    if (n_nodes > MAX_NODES) n_nodes = MAX_NODES;

    int tblocks = (n_nodes + TILE_N - 1) / TILE_N;
    transpose_fold_sign_kernel<<<tblocks, 256>>>(phi_pos, deg_pos, 0, n_nodes);
    transpose_fold_sign_kernel<<<tblocks, 256>>>(phi_neg, deg_neg, 8, n_nodes);

    int total   = nq * H_DIM;
    int gblocks = (total + 255) / 256;
    gather_dot_kernel<<<gblocks, 256>>>(q_phi, k_idx, (float*)d_out, nq);
}

// round 16
// speedup vs baseline: 1.2762x; 1.2762x over previous
#include <cuda_runtime.h>
#include <cuda_fp16.h>
#include <cstdint>

// Problem constants (fixed-shape problem: H=8, MH=8, N_NODES=500000)
#define H_DIM 8
#define MH_DIM 8
#define FEAT 64              // H*MH per sign
#define REC 128              // 2 signs * FEAT values per node record
#define MAX_NODES 500000
#define TILE_N 64            // nodes per transpose tile (R13-proven)

// Node-major scratch in fp16: [node][sign][h][mh], 256B per node,
// deg-normalization folded in. uint4 type guarantees 16B alignment.
__device__ uint4 g_pk_raw[(size_t)MAX_NODES * REC / 8];

// ---- L2 eviction-priority helpers (cache_hint form) ----
__device__ __forceinline__ uint64_t mk_evict_last_policy() {
    uint64_t pol;
    asm("createpolicy.fractional.L2::evict_last.b64 %0, 1.0;" : "=l"(pol));
    return pol;
}
__device__ __forceinline__ void st_hint_v4(void* p, uint4 v, uint64_t pol) {
    asm volatile("st.global.L2::cache_hint.v4.b32 [%0], {%1,%2,%3,%4}, %5;"
                 :: "l"(p), "r"(v.x), "r"(v.y), "r"(v.z), "r"(v.w), "l"(pol));
}
__device__ __forceinline__ uint4 ld_hint_v4(const void* p, uint64_t pol) {
    uint4 r;
    asm volatile("ld.global.L2::cache_hint.v4.u32 {%0,%1,%2,%3}, [%4], %5;"
                 : "=r"(r.x), "=r"(r.y), "=r"(r.z), "=r"(r.w)
                 : "l"(p), "l"(pol));
    return r;
}

// Swizzled byte offset of (feat f, node n) in the 64x64 float tile
// (row = 256B). Conflict-free phase-1 stores, <=2-way phase-2 reads.
// (R13-proven.)
__device__ __forceinline__ int sw_byte(int f, int n) {
    int off = f * 256 + n * 4;
    int x = ((off >> 7) ^ (off >> 11)) & 7;
    return off ^ (x << 4);
}

// ---------------------------------------------------------------------------
// Kernel 1: transpose [h][mh][N] -> scratch[k][sign][h][mh] fp16, folding
// 1/max(deg,1). Block: 256 threads, tile 64 nodes x 64 features.
// gridDim.y = sign; x varies fastest in dispatch, so all pos-sign blocks run
// before neg-sign blocks -> per-SM TLB working set stays ~75 2MB pages
// (64 phi rows of one sign + deg + scratch), as in the R13 two-launch form,
// while saving one launch bubble.
// ---------------------------------------------------------------------------
__global__ __launch_bounds__(256) void transpose_fold_sign_kernel(
    const float* __restrict__ phi_pos,
    const float* __restrict__ phi_neg,
    const float* __restrict__ deg_pos,
    const float* __restrict__ deg_neg,
    int n_nodes)
{
    __shared__ __align__(16) char tile_raw[64 * 256];    // 16KB
    __shared__ float inv[TILE_N][H_DIM];                 // 2KB

    const int sgn = blockIdx.y;                 // 0 = pos, 1 = neg
    const float* __restrict__ phi = sgn ? phi_neg : phi_pos;
    const float* __restrict__ deg = sgn ? deg_neg : deg_pos;
    const int sgn8 = sgn * 8;                   // chunk offset in record

    const int k0 = blockIdx.x * TILE_N;
    const int t  = threadIdx.x;
    const uint64_t pol = mk_evict_last_policy();
    const bool full = (k0 + TILE_N <= n_nodes) && ((n_nodes & 3) == 0);

    // ---- inv table: 64 nodes * 8 heads = 512 values ----
    // (consumed only in phase 2; the phase-1->2 barrier provides ordering)
    #pragma unroll
    for (int it = 0; it < 2; ++it) {
        int idx  = t + it * 256;            // node*8 + h
        int node = idx >> 3;
        int h    = idx & 7;
        int k    = k0 + node;
        float d  = 1.0f;
        if (k < n_nodes)
            d = __ldcs(deg + (size_t)k * H_DIM + h);
        inv[node][h] = 1.0f / fmaxf(d, 1.0f);
    }

    // ---- phase 1: 64 feat-rows x 16 float4 groups (64 nodes) ----
    if (full) {
        #pragma unroll
        for (int it = 0; it < 4; ++it) {
            int l = t + it * 256;           // 0..1023
            int f = l >> 4;                 // feat row 0..63
            int g = l & 15;                 // float4 group (4 nodes)
            float4 v = __ldcs(reinterpret_cast<const float4*>(
                phi + (size_t)f * n_nodes + k0 + 4 * g));
            *reinterpret_cast<float4*>(tile_raw + sw_byte(f, 4 * g)) = v;
        }
    } else {
        #pragma unroll 4
        for (int it = 0; it < 16; ++it) {
            int l  = t + it * 256;          // 64*64 = 4096 elements
            int f  = l >> 6;
            int kk = l & 63;
            int k  = k0 + kk;
            float v = 0.0f;
            if (k < n_nodes)
                v = __ldcs(phi + (size_t)f * n_nodes + k);
            *reinterpret_cast<float*>(tile_raw + sw_byte(f, kk)) = v;
        }
    }
    __syncthreads();

    // ---- phase 2: 64 nodes x 8 chunks; chunk c = head c = feats 8c..8c+7 ----
    #pragma unroll
    for (int it = 0; it < 2; ++it) {
        int l    = t + it * 256;            // 0..511
        int node = l >> 3;
        int c    = l & 7;
        int k    = k0 + node;
        if (k < n_nodes) {
            float sc = inv[node][c];
            __half2 hh[4];
            #pragma unroll
            for (int j = 0; j < 8; j += 2) {
                float a = *reinterpret_cast<const float*>(
                              tile_raw + sw_byte(8 * c + j, node)) * sc;
                float b = *reinterpret_cast<const float*>(
                              tile_raw + sw_byte(8 * c + j + 1, node)) * sc;
                hh[j >> 1] = __floats2half2_rn(a, b);
            }
            uint4 val;
            __builtin_memcpy(&val, hh, 16);
            st_hint_v4(g_pk_raw + (size_t)k * (REC / 8) + sgn8 + c, val, pol);
        }
    }
}

// ---------------------------------------------------------------------------
// Kernel 2: gather + dot (champion, byte-identical). 8 threads per query;
// thread j = head j. out layout: [pos: nq*8][neg: nq*8]
// ---------------------------------------------------------------------------
__global__ __launch_bounds__(256) void gather_dot_kernel(
    const float* __restrict__ q_phi,
    const int*   __restrict__ k_indices,
    float* __restrict__ out,
    int nq)
{
    int t = blockIdx.x * blockDim.x + threadIdx.x;
    int i = t >> 3;
    if (i >= nq) return;
    int h = t & 7;

    const uint64_t pol = mk_evict_last_policy();

    int k = __ldcs(k_indices + i);

    const float4* qp = reinterpret_cast<const float4*>(
        q_phi + (size_t)i * FEAT + h * MH_DIM);
    float4 q0 = __ldcs(qp);
    float4 q1 = __ldcs(qp + 1);

    const uint4* rec = g_pk_raw + (size_t)k * (REC / 8);
    uint4 pr = ld_hint_v4(rec + h, pol);
    uint4 nr = ld_hint_v4(rec + 8 + h, pol);

    const __half2* ph = reinterpret_cast<const __half2*>(&pr);
    const __half2* nh = reinterpret_cast<const __half2*>(&nr);

    float2 p0 = __half22float2(ph[0]);
    float2 p1 = __half22float2(ph[1]);
    float2 p2 = __half22float2(ph[2]);
    float2 p3 = __half22float2(ph[3]);
    float2 n0 = __half22float2(nh[0]);
    float2 n1 = __half22float2(nh[1]);
    float2 n2 = __half22float2(nh[2]);
    float2 n3 = __half22float2(nh[3]);

    float dp = q0.x * p0.x + q0.y * p0.y + q0.z * p1.x + q0.w * p1.y
             + q1.x * p2.x + q1.y * p2.y + q1.z * p3.x + q1.w * p3.y;
    float dn = q0.x * n0.x + q0.y * n0.y + q0.z * n1.x + q0.w * n1.y
             + q1.x * n2.x + q1.y * n2.y + q1.z * n3.x + q1.w * n3.y;

    __stcs(out + (size_t)i * H_DIM + h, dp);
    __stcs(out + (size_t)nq * H_DIM + (size_t)i * H_DIM + h, dn);
}

extern "C" void kernel_launch(void* const* d_in, const int* in_sizes, int n_in,
                              void* d_out, int out_size)
{
    const float* q_phi   = (const float*)d_in[0];
    const float* phi_pos = (const float*)d_in[1];
    const float* phi_neg = (const float*)d_in[2];
    const float* deg_pos = (const float*)d_in[3];
    const float* deg_neg = (const float*)d_in[4];
    const int*   k_idx   = (const int*)d_in[5];

    int nq      = in_sizes[5];                    // k_indices has N_Q elements
    int n_nodes = in_sizes[3] / H_DIM;            // deg_pos is [N][H]
    if (n_nodes > MAX_NODES) n_nodes = MAX_NODES;

    int tblocks = (n_nodes + TILE_N - 1) / TILE_N;
    dim3 tgrid(tblocks, 2);                       // y = sign; x dispatched first
    transpose_fold_sign_kernel<<<tgrid, 256>>>(phi_pos, phi_neg,
                                               deg_pos, deg_neg, n_nodes);

    int total   = nq * H_DIM;
    int gblocks = (total + 255) / 256;
    gather_dot_kernel<<<gblocks, 256>>>(q_phi, k_idx, (float*)d_out, nq);
}